// round 5
// baseline (speedup 1.0000x reference)
#include <cuda_runtime.h>
#include <cuda_fp16.h>
#include <cstdint>

#define DINL __device__ __forceinline__

namespace {
constexpr int KDIM = 4096;   // in_features
constexpr int NOUT = 4096;   // out_features
constexpr int MTOK = 1024;   // tokens

constexpr int BM = 128;      // CTA tile M
constexpr int BN = 256;      // CTA tile N
constexpr int BK = 32;       // K per stage
constexpr int NUM_K = KDIM / BK;   // 128
constexpr int STAGES = 4;
constexpr int THREADS = 512; // 16 warps: 4 in M x 4 in N

constexpr int A_ROW_B = 80;                 // 32 halves (64B) + 16B pad -> conflict-free ldmatrix
constexpr int B_ROW_B = 80;
constexpr int A_BYTES = BM * A_ROW_B;       // 10240
constexpr int B_BYTES = BN * B_ROW_B;       // 20480
constexpr int STAGE_BYTES = A_BYTES + B_BYTES;   // 30720
constexpr int SMEM_TOTAL = STAGES * STAGE_BYTES; // 122880

constexpr int CONV_BLOCKS = (MTOK * KDIM / 4) / 256;            // 4096
constexpr int PACK_BLOCKS = (NOUT * (KDIM / 128) * 32) / 256;   // 16384
}  // namespace

// Scratch (static device globals: allowed; no runtime allocation).
__device__ __align__(16) __half   g_xh[(size_t)MTOK * KDIM];          // 8 MB fp16 x
__device__ __align__(16) unsigned g_wbits[(KDIM / 32) * NOUT];        // 2 MB packed binarized W, [kchunk][n]

DINL uint32_t smem_u32(const void* p) {
    uint32_t a;
    asm("{ .reg .u64 t; cvta.to.shared.u64 t, %1; cvt.u32.u64 %0, t; }" : "=r"(a) : "l"(p));
    return a;
}

// ---------------- fused prepass: x->fp16  +  binarize/bit-pack W ----------------
__global__ void __launch_bounds__(256) prepass_kernel(const float* __restrict__ x,
                                                      const float* __restrict__ w) {
    if (blockIdx.x < CONV_BLOCKS) {
        int i = blockIdx.x * blockDim.x + threadIdx.x;
        float4 v = __ldcs((const float4*)x + i);            // read-once: stream past L2
        __half2 h0 = __floats2half2_rn(v.x, v.y);
        __half2 h1 = __floats2half2_rn(v.z, v.w);
        uint2 u;
        u.x = *(const uint32_t*)&h0;
        u.y = *(const uint32_t*)&h1;
        *(uint2*)(&g_xh[(size_t)i * 4]) = u;                // re-read by GEMM: keep cacheable
    } else {
        // one warp packs 128 K-values (float4/lane) of one W row into 4 bit-words
        int pb = blockIdx.x - CONV_BLOCKS;
        int lane = threadIdx.x & 31;
        int wg = pb * 8 + (threadIdx.x >> 5);   // global warp id
        int n = wg & (NOUT - 1);
        int kb = wg >> 12;                      // 128-wide K block, 0..31
        const float4 v = __ldcs((const float4*)(w + (size_t)n * KDIM + kb * 128) + lane);
        unsigned nib = (v.x > 0.f ? 1u : 0u) | (v.y > 0.f ? 2u : 0u)
                     | (v.z > 0.f ? 4u : 0u) | (v.w > 0.f ? 8u : 0u);
        unsigned a = nib | (__shfl_down_sync(0xFFFFFFFFu, nib, 1) << 4);
        unsigned b = a   | (__shfl_down_sync(0xFFFFFFFFu, a, 2)   << 8);
        unsigned m = b   | (__shfl_down_sync(0xFFFFFFFFu, b, 4)   << 16);
        if ((lane & 7) == 0) {
            int c = kb * 4 + (lane >> 3);
            g_wbits[c * NOUT + n] = m;
        }
    }
}

// ---------------- main GEMM: out = (x_fp16 @ Wb^T) * round(max(s,1)) ----------------
// f16-accumulate HMMA (2x rate); fp32 promotion every 2 K-chunks on the tensor pipe
// (identity-B f32-accum HMMA). 16 warps (4 warps/SMSP) for latency hiding.
__global__ void __launch_bounds__(THREADS, 1)
SBNLinear_39754217292616_kernel(const float* __restrict__ s, float* __restrict__ out) {
    extern __shared__ char smem[];
    const uint32_t sb = smem_u32(smem);
    const int tid = threadIdx.x;
    const int lane = tid & 31;
    const int wid = tid >> 5;                 // 0..15
    const int m0 = blockIdx.x * BM;
    const int n0 = blockIdx.y * BN;
    const int m_off = (wid >> 2) * 32;        // 4 warps in M, 32 rows each
    const int n_off = (wid & 3) * 64;         // 4 warps in N, 64 cols each

    // identity B-fragment (fp16 I8), same register for both k-halves
    const int q = lane >> 2, p = lane & 3;
    const uint32_t idf = ((2 * p == q) ? 0x3C00u : 0u) | ((2 * p + 1 == q) ? 0x3C000000u : 0u);
    const uint32_t zf = 0u;

    float acc32[2][8][4];
    uint32_t acc16[2][8][2];
    #pragma unroll
    for (int mi = 0; mi < 2; ++mi)
        #pragma unroll
        for (int nj = 0; nj < 8; ++nj) {
            acc16[mi][nj][0] = 0u; acc16[mi][nj][1] = 0u;
            #pragma unroll
            for (int e = 0; e < 4; ++e) acc32[mi][nj][e] = 0.0f;
        }

    // one cp.async per thread covers the whole A tile (128 rows x 4 x 16B)
    auto issueA = [&](int c, int buf) {
        int row = tid >> 2;
        int ch = tid & 3;
        uint32_t dst = sb + buf * STAGE_BYTES + row * A_ROW_B + ch * 16;
        const __half* src = &g_xh[(size_t)(m0 + row) * KDIM + c * BK + ch * 8];
        asm volatile("cp.async.cg.shared.global [%0], [%1], 16;\n" :: "r"(dst), "l"(src) : "memory");
    };
    // two threads per B row: each expands 16 bits -> 16 fp16 (32B) of the row
    auto stsB = [&](unsigned bits16, int buf) {
        int row = tid >> 1;
        int half = tid & 1;
        uint32_t dst = sb + buf * STAGE_BYTES + A_BYTES + row * B_ROW_B + half * 32;
        #pragma unroll
        for (int j = 0; j < 2; ++j) {
            uint32_t u0, u1, u2, u3;
            int pp = j * 8;
            u0 = ((bits16 >> (pp + 0)) & 1 ? 0x3C00u : 0u) | ((bits16 >> (pp + 1)) & 1 ? 0x3C000000u : 0u);
            u1 = ((bits16 >> (pp + 2)) & 1 ? 0x3C00u : 0u) | ((bits16 >> (pp + 3)) & 1 ? 0x3C000000u : 0u);
            u2 = ((bits16 >> (pp + 4)) & 1 ? 0x3C00u : 0u) | ((bits16 >> (pp + 5)) & 1 ? 0x3C000000u : 0u);
            u3 = ((bits16 >> (pp + 6)) & 1 ? 0x3C00u : 0u) | ((bits16 >> (pp + 7)) & 1 ? 0x3C000000u : 0u);
            asm volatile("st.shared.v4.b32 [%0], {%1,%2,%3,%4};\n"
                         :: "r"(dst + j * 16), "r"(u0), "r"(u1), "r"(u2), "r"(u3) : "memory");
        }
    };
    auto loadBits = [&](int c) -> unsigned {
        unsigned bits = g_wbits[c * NOUT + n0 + (tid >> 1)];
        return (bits >> (16 * (tid & 1))) & 0xFFFFu;
    };

    // prologue: stages 0..2
    #pragma unroll
    for (int c = 0; c < STAGES - 1; ++c) {
        issueA(c, c);
        asm volatile("cp.async.commit_group;\n" ::: "memory");
        stsB(loadBits(c), c);
    }
    unsigned bits_next = loadBits(3);

    for (int c = 0; c < NUM_K; ++c) {
        const int buf = c & 3;
        if (c < NUM_K - 2)       asm volatile("cp.async.wait_group 2;\n" ::: "memory");
        else if (c == NUM_K - 2) asm volatile("cp.async.wait_group 1;\n" ::: "memory");
        else                     asm volatile("cp.async.wait_group 0;\n" ::: "memory");
        __syncthreads();

        const int cn = c + 3;
        if (cn < NUM_K) {
            const int nbuf = cn & 3;
            stsB(bits_next, nbuf);
            issueA(cn, nbuf);
            asm volatile("cp.async.commit_group;\n" ::: "memory");
            if (cn + 1 < NUM_K)
                bits_next = loadBits(cn + 1);
        }

        const uint32_t ab = sb + buf * STAGE_BYTES;
        const uint32_t bb = ab + A_BYTES;
        #pragma unroll
        for (int h = 0; h < 2; ++h) {
            uint32_t a[2][4];
            #pragma unroll
            for (int mi = 0; mi < 2; ++mi) {
                uint32_t addr = ab + (uint32_t)(m_off + 16 * mi + (lane & 15)) * A_ROW_B
                                   + (uint32_t)(2 * h + (lane >> 4)) * 16;
                asm volatile("ldmatrix.sync.aligned.m8n8.x4.shared.b16 {%0,%1,%2,%3}, [%4];\n"
                             : "=r"(a[mi][0]), "=r"(a[mi][1]), "=r"(a[mi][2]), "=r"(a[mi][3])
                             : "r"(addr));
            }
            #pragma unroll
            for (int g = 0; g < 4; ++g) {
                int row = n_off + 16 * g + ((lane >> 4) << 3) + (lane & 7);
                uint32_t addr = bb + (uint32_t)row * B_ROW_B
                                   + (uint32_t)(2 * h + ((lane >> 3) & 1)) * 16;
                uint32_t r0, r1, r2, r3;
                asm volatile("ldmatrix.sync.aligned.m8n8.x4.shared.b16 {%0,%1,%2,%3}, [%4];\n"
                             : "=r"(r0), "=r"(r1), "=r"(r2), "=r"(r3) : "r"(addr));
                #pragma unroll
                for (int mi = 0; mi < 2; ++mi) {
                    asm volatile(
                        "mma.sync.aligned.m16n8k16.row.col.f16.f16.f16.f16 "
                        "{%0,%1}, {%2,%3,%4,%5}, {%6,%7}, {%0,%1};\n"
                        : "+r"(acc16[mi][2 * g][0]), "+r"(acc16[mi][2 * g][1])
                        : "r"(a[mi][0]), "r"(a[mi][1]), "r"(a[mi][2]), "r"(a[mi][3]),
                          "r"(r0), "r"(r1));
                    asm volatile(
                        "mma.sync.aligned.m16n8k16.row.col.f16.f16.f16.f16 "
                        "{%0,%1}, {%2,%3,%4,%5}, {%6,%7}, {%0,%1};\n"
                        : "+r"(acc16[mi][2 * g + 1][0]), "+r"(acc16[mi][2 * g + 1][1])
                        : "r"(a[mi][0]), "r"(a[mi][1]), "r"(a[mi][2]), "r"(a[mi][3]),
                          "r"(r2), "r"(r3));
                }
            }
        }

        // promote f16 segment accumulators into fp32 every 2 chunks, on the tensor pipe
        if (c & 1) {
            #pragma unroll
            for (int mi = 0; mi < 2; ++mi)
                #pragma unroll
                for (int g = 0; g < 4; ++g) {
                    asm volatile(
                        "mma.sync.aligned.m16n8k16.row.col.f32.f16.f16.f32 "
                        "{%0,%1,%2,%3}, {%4,%5,%6,%7}, {%8,%9}, {%0,%1,%2,%3};\n"
                        : "+f"(acc32[mi][2 * g][0]), "+f"(acc32[mi][2 * g][1]),
                          "+f"(acc32[mi][2 * g][2]), "+f"(acc32[mi][2 * g][3])
                        : "r"(acc16[mi][2 * g][0]), "r"(acc16[mi][2 * g][1]),
                          "r"(acc16[mi][2 * g + 1][0]), "r"(acc16[mi][2 * g + 1][1]),
                          "r"(idf), "r"(zf));
                    asm volatile(
                        "mma.sync.aligned.m16n8k16.row.col.f32.f16.f16.f32 "
                        "{%0,%1,%2,%3}, {%4,%5,%6,%7}, {%8,%9}, {%0,%1,%2,%3};\n"
                        : "+f"(acc32[mi][2 * g + 1][0]), "+f"(acc32[mi][2 * g + 1][1]),
                          "+f"(acc32[mi][2 * g + 1][2]), "+f"(acc32[mi][2 * g + 1][3])
                        : "r"(acc16[mi][2 * g][0]), "r"(acc16[mi][2 * g][1]),
                          "r"(acc16[mi][2 * g + 1][0]), "r"(acc16[mi][2 * g + 1][1]),
                          "r"(zf), "r"(idf));
                    acc16[mi][2 * g][0] = 0u;     acc16[mi][2 * g][1] = 0u;
                    acc16[mi][2 * g + 1][0] = 0u; acc16[mi][2 * g + 1][1] = 0u;
                }
        }
    }

    // epilogue: fuse s_eff = rint(max(s,1)) and store
    float sc[8][2];
    #pragma unroll
    for (int nj = 0; nj < 8; ++nj) {
        int col = n0 + n_off + 8 * nj + 2 * (lane & 3);
        sc[nj][0] = rintf(fmaxf(s[col], 1.0f));
        sc[nj][1] = rintf(fmaxf(s[col + 1], 1.0f));
    }
    #pragma unroll
    for (int mi = 0; mi < 2; ++mi) {
        int r0 = m0 + m_off + 16 * mi + (lane >> 2);
        #pragma unroll
        for (int nj = 0; nj < 8; ++nj) {
            int col = n0 + n_off + 8 * nj + 2 * (lane & 3);
            float2 v0 = make_float2(acc32[mi][nj][0] * sc[nj][0], acc32[mi][nj][1] * sc[nj][1]);
            float2 v1 = make_float2(acc32[mi][nj][2] * sc[nj][0], acc32[mi][nj][3] * sc[nj][1]);
            *(float2*)(out + (size_t)r0 * NOUT + col) = v0;
            *(float2*)(out + (size_t)(r0 + 8) * NOUT + col) = v1;
        }
    }
}

extern "C" void kernel_launch(void* const* d_in, const int* in_sizes, int n_in,
                              void* d_out, int out_size) {
    (void)in_sizes; (void)n_in; (void)out_size;
    const float* x = (const float*)d_in[0];
    const float* w = (const float*)d_in[1];
    const float* s = (const float*)d_in[2];
    float* out = (float*)d_out;

    prepass_kernel<<<CONV_BLOCKS + PACK_BLOCKS, 256>>>(x, w);

    cudaFuncSetAttribute(SBNLinear_39754217292616_kernel,
                         cudaFuncAttributeMaxDynamicSharedMemorySize, SMEM_TOTAL);
    dim3 grid(MTOK / BM, NOUT / BN);   // 8 x 16 = 128 CTAs
    SBNLinear_39754217292616_kernel<<<grid, THREADS, SMEM_TOTAL>>>(s, out);
}

// round 6
// speedup vs baseline: 1.3004x; 1.3004x over previous
#include <cuda_runtime.h>
#include <cuda_fp16.h>
#include <cstdint>

#define DINL __device__ __forceinline__

namespace {
constexpr int KDIM = 4096;   // in_features
constexpr int NOUT = 4096;   // out_features
constexpr int MTOK = 1024;   // tokens

constexpr int BM = 128;      // CTA tile M
constexpr int BN = 256;      // CTA tile N
constexpr int BK = 64;       // K per stage (chunk)
constexpr int NUM_K = KDIM / BK;   // 64
constexpr int STAGES = 3;
constexpr int THREADS = 256; // 8 warps: 2 in M x 4 in N (64x64 per warp)

constexpr int A_ROW_B = 144;                // 64 halves (128B) + 16B pad -> conflict-free ldmatrix
constexpr int B_ROW_B = 144;
constexpr int A_BYTES = BM * A_ROW_B;       // 18432
constexpr int B_BYTES = BN * B_ROW_B;       // 36864
constexpr int STAGE_BYTES = A_BYTES + B_BYTES;   // 55296
constexpr int SMEM_TOTAL = STAGES * STAGE_BYTES; // 165888

constexpr int CONV_BLOCKS = (MTOK * KDIM / 16) / 256;           // 1024  (4 float4/thread)
constexpr int PACK_BLOCKS = (NOUT * (KDIM / 256)) / 8;          // 8192  (1 warp = 256 K-values)
}  // namespace

// Scratch (static device globals: allowed; no runtime allocation).
__device__ __align__(16) __half   g_xh[(size_t)MTOK * KDIM];          // 8 MB fp16 x
__device__ __align__(16) unsigned g_wbits[(KDIM / 32) * NOUT];        // 2 MB packed binarized W, [kword][n]

DINL uint32_t smem_u32(const void* p) {
    uint32_t a;
    asm("{ .reg .u64 t; cvta.to.shared.u64 t, %1; cvt.u32.u64 %0, t; }" : "=r"(a) : "l"(p));
    return a;
}

// ---------------- fused prepass: x->fp16  +  binarize/bit-pack W ----------------
__global__ void __launch_bounds__(256) prepass_kernel(const float* __restrict__ x,
                                                      const float* __restrict__ w) {
    if (blockIdx.x < CONV_BLOCKS) {
        // 4 independent float4 per thread (MLP=4)
        int base = blockIdx.x * 256 + threadIdx.x;
        float4 v[4];
        #pragma unroll
        for (int j = 0; j < 4; ++j)
            v[j] = __ldcs((const float4*)x + base + j * (CONV_BLOCKS * 256));
        #pragma unroll
        for (int j = 0; j < 4; ++j) {
            __half2 h0 = __floats2half2_rn(v[j].x, v[j].y);
            __half2 h1 = __floats2half2_rn(v[j].z, v[j].w);
            uint2 u;
            u.x = *(const uint32_t*)&h0;
            u.y = *(const uint32_t*)&h1;
            *(uint2*)(&g_xh[(size_t)(base + j * (CONV_BLOCKS * 256)) * 4]) = u;
        }
    } else {
        // one warp packs 256 K-values (2x float4/lane) of one W row into 8 bit-words
        int pb = blockIdx.x - CONV_BLOCKS;
        int lane = threadIdx.x & 31;
        int wg = pb * 8 + (threadIdx.x >> 5);   // global warp id
        int n = wg & (NOUT - 1);
        int kb = wg >> 12;                      // 256-wide K block, 0..15
        const float4* src = (const float4*)(w + (size_t)n * KDIM + kb * 256);
        const float4 v0 = __ldcs(src + lane);
        const float4 v1 = __ldcs(src + 32 + lane);
        #pragma unroll
        for (int half = 0; half < 2; ++half) {
            const float4& v = half ? v1 : v0;
            unsigned nib = (v.x > 0.f ? 1u : 0u) | (v.y > 0.f ? 2u : 0u)
                         | (v.z > 0.f ? 4u : 0u) | (v.w > 0.f ? 8u : 0u);
            unsigned a = nib | (__shfl_down_sync(0xFFFFFFFFu, nib, 1) << 4);
            unsigned b = a   | (__shfl_down_sync(0xFFFFFFFFu, a, 2)   << 8);
            unsigned m = b   | (__shfl_down_sync(0xFFFFFFFFu, b, 4)   << 16);
            if ((lane & 7) == 0) {
                int c = kb * 8 + half * 4 + (lane >> 3);
                g_wbits[c * NOUT + n] = m;
            }
        }
    }
}

// ---------------- main GEMM: out = (x_fp16 @ Wb^T) * round(max(s,1)) ----------------
// f16-accumulate HMMA; fp32 promotion every chunk (64 K) on the tensor pipe via
// identity-B f32-accum HMMA. BK=64 halves barrier count and doubles ILP window.
__global__ void __launch_bounds__(THREADS, 1)
SBNLinear_39754217292616_kernel(const float* __restrict__ s, float* __restrict__ out) {
    extern __shared__ char smem[];
    const uint32_t sb = smem_u32(smem);
    const int tid = threadIdx.x;
    const int lane = tid & 31;
    const int wid = tid >> 5;
    const int m0 = blockIdx.x * BM;
    const int n0 = blockIdx.y * BN;
    const int m_off = (wid >> 2) * 64;     // 2 warps in M
    const int n_off = (wid & 3) * 64;      // 4 warps in N

    // identity B-fragment (fp16 I8), same register for both k-halves
    const int q = lane >> 2, p = lane & 3;
    const uint32_t idf = ((2 * p == q) ? 0x3C00u : 0u) | ((2 * p + 1 == q) ? 0x3C000000u : 0u);
    const uint32_t zf = 0u;

    float acc32[4][8][4];
    uint32_t acc16[4][8][2];
    #pragma unroll
    for (int mi = 0; mi < 4; ++mi)
        #pragma unroll
        for (int nj = 0; nj < 8; ++nj) {
            acc16[mi][nj][0] = 0u; acc16[mi][nj][1] = 0u;
            #pragma unroll
            for (int e = 0; e < 4; ++e) acc32[mi][nj][e] = 0.0f;
        }

    // A tile: 128 rows x 128B = 1024 x 16B, 4 cp.async per thread
    auto issueA = [&](int c, int buf) {
        #pragma unroll
        for (int i = 0; i < 4; ++i) {
            int qx = tid + i * THREADS;          // 0..1023
            int row = qx >> 3;
            int ch = qx & 7;
            uint32_t dst = sb + buf * STAGE_BYTES + row * A_ROW_B + ch * 16;
            const __half* src = &g_xh[(size_t)(m0 + row) * KDIM + c * BK + ch * 8];
            asm volatile("cp.async.cg.shared.global [%0], [%1], 16;\n" :: "r"(dst), "l"(src) : "memory");
        }
    };
    // one thread per B row: expand 64 bits -> 64 fp16 {0,1} (128B)
    auto stsB = [&](uint2 bits, int buf) {
        uint32_t dst = sb + buf * STAGE_BYTES + A_BYTES + tid * B_ROW_B;
        #pragma unroll
        for (int j = 0; j < 8; ++j) {
            unsigned b8 = ((j < 4 ? bits.x : bits.y) >> ((j & 3) * 8)) & 0xFFu;
            uint32_t u0, u1, u2, u3;
            u0 = (b8 & 1u   ? 0x3C00u : 0u) | (b8 & 2u   ? 0x3C000000u : 0u);
            u1 = (b8 & 4u   ? 0x3C00u : 0u) | (b8 & 8u   ? 0x3C000000u : 0u);
            u2 = (b8 & 16u  ? 0x3C00u : 0u) | (b8 & 32u  ? 0x3C000000u : 0u);
            u3 = (b8 & 64u  ? 0x3C00u : 0u) | (b8 & 128u ? 0x3C000000u : 0u);
            asm volatile("st.shared.v4.b32 [%0], {%1,%2,%3,%4};\n"
                         :: "r"(dst + j * 16), "r"(u0), "r"(u1), "r"(u2), "r"(u3) : "memory");
        }
    };
    auto loadBits = [&](int c) -> uint2 {
        uint2 r;
        r.x = g_wbits[(2 * c) * NOUT + n0 + tid];
        r.y = g_wbits[(2 * c + 1) * NOUT + n0 + tid];
        return r;
    };

    // prologue: stages 0..1
    #pragma unroll
    for (int c = 0; c < STAGES - 1; ++c) {
        issueA(c, c);
        asm volatile("cp.async.commit_group;\n" ::: "memory");
        stsB(loadBits(c), c);
    }
    uint2 bits_next = loadBits(2);

    for (int c = 0; c < NUM_K; ++c) {
        const int buf = c % 3;
        if (c < NUM_K - 2) asm volatile("cp.async.wait_group 1;\n" ::: "memory");
        else               asm volatile("cp.async.wait_group 0;\n" ::: "memory");
        __syncthreads();

        const int cn = c + 2;
        if (cn < NUM_K) {
            const int nbuf = cn % 3;
            stsB(bits_next, nbuf);
            issueA(cn, nbuf);
            asm volatile("cp.async.commit_group;\n" ::: "memory");
            if (cn + 1 < NUM_K)
                bits_next = loadBits(cn + 1);
        }

        const uint32_t ab = sb + buf * STAGE_BYTES;
        const uint32_t bb = ab + A_BYTES;
        #pragma unroll
        for (int h = 0; h < 4; ++h) {
            uint32_t a[4][4];
            #pragma unroll
            for (int mi = 0; mi < 4; ++mi) {
                uint32_t addr = ab + (uint32_t)(m_off + 16 * mi + (lane & 15)) * A_ROW_B
                                   + (uint32_t)(2 * h + (lane >> 4)) * 16;
                asm volatile("ldmatrix.sync.aligned.m8n8.x4.shared.b16 {%0,%1,%2,%3}, [%4];\n"
                             : "=r"(a[mi][0]), "=r"(a[mi][1]), "=r"(a[mi][2]), "=r"(a[mi][3])
                             : "r"(addr));
            }
            #pragma unroll
            for (int g = 0; g < 4; ++g) {
                int row = n_off + 16 * g + ((lane >> 4) << 3) + (lane & 7);
                uint32_t addr = bb + (uint32_t)row * B_ROW_B
                                   + (uint32_t)(2 * h + ((lane >> 3) & 1)) * 16;
                uint32_t r0, r1, r2, r3;
                asm volatile("ldmatrix.sync.aligned.m8n8.x4.shared.b16 {%0,%1,%2,%3}, [%4];\n"
                             : "=r"(r0), "=r"(r1), "=r"(r2), "=r"(r3) : "r"(addr));
                #pragma unroll
                for (int mi = 0; mi < 4; ++mi) {
                    asm volatile(
                        "mma.sync.aligned.m16n8k16.row.col.f16.f16.f16.f16 "
                        "{%0,%1}, {%2,%3,%4,%5}, {%6,%7}, {%0,%1};\n"
                        : "+r"(acc16[mi][2 * g][0]), "+r"(acc16[mi][2 * g][1])
                        : "r"(a[mi][0]), "r"(a[mi][1]), "r"(a[mi][2]), "r"(a[mi][3]),
                          "r"(r0), "r"(r1));
                    asm volatile(
                        "mma.sync.aligned.m16n8k16.row.col.f16.f16.f16.f16 "
                        "{%0,%1}, {%2,%3,%4,%5}, {%6,%7}, {%0,%1};\n"
                        : "+r"(acc16[mi][2 * g + 1][0]), "+r"(acc16[mi][2 * g + 1][1])
                        : "r"(a[mi][0]), "r"(a[mi][1]), "r"(a[mi][2]), "r"(a[mi][3]),
                          "r"(r2), "r"(r3));
                }
            }
        }

        // promote f16 segment accumulators (64 K-steps) into fp32 on the tensor pipe
        #pragma unroll
        for (int mi = 0; mi < 4; ++mi)
            #pragma unroll
            for (int g = 0; g < 4; ++g) {
                asm volatile(
                    "mma.sync.aligned.m16n8k16.row.col.f32.f16.f16.f32 "
                    "{%0,%1,%2,%3}, {%4,%5,%6,%7}, {%8,%9}, {%0,%1,%2,%3};\n"
                    : "+f"(acc32[mi][2 * g][0]), "+f"(acc32[mi][2 * g][1]),
                      "+f"(acc32[mi][2 * g][2]), "+f"(acc32[mi][2 * g][3])
                    : "r"(acc16[mi][2 * g][0]), "r"(acc16[mi][2 * g][1]),
                      "r"(acc16[mi][2 * g + 1][0]), "r"(acc16[mi][2 * g + 1][1]),
                      "r"(idf), "r"(zf));
                asm volatile(
                    "mma.sync.aligned.m16n8k16.row.col.f32.f16.f16.f32 "
                    "{%0,%1,%2,%3}, {%4,%5,%6,%7}, {%8,%9}, {%0,%1,%2,%3};\n"
                    : "+f"(acc32[mi][2 * g + 1][0]), "+f"(acc32[mi][2 * g + 1][1]),
                      "+f"(acc32[mi][2 * g + 1][2]), "+f"(acc32[mi][2 * g + 1][3])
                    : "r"(acc16[mi][2 * g][0]), "r"(acc16[mi][2 * g][1]),
                      "r"(acc16[mi][2 * g + 1][0]), "r"(acc16[mi][2 * g + 1][1]),
                      "r"(zf), "r"(idf));
                acc16[mi][2 * g][0] = 0u;     acc16[mi][2 * g][1] = 0u;
                acc16[mi][2 * g + 1][0] = 0u; acc16[mi][2 * g + 1][1] = 0u;
            }
    }

    // epilogue: fuse s_eff = rint(max(s,1)) and store
    float sc[8][2];
    #pragma unroll
    for (int nj = 0; nj < 8; ++nj) {
        int col = n0 + n_off + 8 * nj + 2 * (lane & 3);
        sc[nj][0] = rintf(fmaxf(s[col], 1.0f));
        sc[nj][1] = rintf(fmaxf(s[col + 1], 1.0f));
    }
    #pragma unroll
    for (int mi = 0; mi < 4; ++mi) {
        int r0 = m0 + m_off + 16 * mi + (lane >> 2);
        #pragma unroll
        for (int nj = 0; nj < 8; ++nj) {
            int col = n0 + n_off + 8 * nj + 2 * (lane & 3);
            float2 v0 = make_float2(acc32[mi][nj][0] * sc[nj][0], acc32[mi][nj][1] * sc[nj][1]);
            float2 v1 = make_float2(acc32[mi][nj][2] * sc[nj][0], acc32[mi][nj][3] * sc[nj][1]);
            *(float2*)(out + (size_t)r0 * NOUT + col) = v0;
            *(float2*)(out + (size_t)(r0 + 8) * NOUT + col) = v1;
        }
    }
}

extern "C" void kernel_launch(void* const* d_in, const int* in_sizes, int n_in,
                              void* d_out, int out_size) {
    (void)in_sizes; (void)n_in; (void)out_size;
    const float* x = (const float*)d_in[0];
    const float* w = (const float*)d_in[1];
    const float* s = (const float*)d_in[2];
    float* out = (float*)d_out;

    prepass_kernel<<<CONV_BLOCKS + PACK_BLOCKS, 256>>>(x, w);

    cudaFuncSetAttribute(SBNLinear_39754217292616_kernel,
                         cudaFuncAttributeMaxDynamicSharedMemorySize, SMEM_TOTAL);
    dim3 grid(MTOK / BM, NOUT / BN);   // 8 x 16 = 128 CTAs
    SBNLinear_39754217292616_kernel<<<grid, THREADS, SMEM_TOTAL>>>(s, out);
}

// round 7
// speedup vs baseline: 1.3246x; 1.0186x over previous
#include <cuda_runtime.h>
#include <cuda_fp16.h>
#include <cstdint>

#define DINL __device__ __forceinline__

namespace {
constexpr int KDIM = 4096;   // in_features
constexpr int NOUT = 4096;   // out_features
constexpr int MTOK = 1024;   // tokens

constexpr int BM = 128;      // CTA tile M
constexpr int BN = 128;      // CTA tile N
constexpr int BK = 64;       // K per stage (chunk)
constexpr int NUM_K = KDIM / BK;   // 64
constexpr int STAGES = 3;
constexpr int THREADS = 128; // 4 warps: 2 in M x 2 in N (64x64 per warp)

constexpr int A_ROW_B = 144;                // 64 halves (128B) + 16B pad -> conflict-free ldmatrix
constexpr int B_ROW_B = 144;
constexpr int A_BYTES = BM * A_ROW_B;       // 18432
constexpr int B_BYTES = BN * B_ROW_B;       // 18432
constexpr int STAGE_BYTES = A_BYTES + B_BYTES;   // 36864
constexpr int SMEM_TOTAL = STAGES * STAGE_BYTES; // 110592  -> 2 CTAs/SM

constexpr int CONV_BLOCKS = (MTOK * KDIM / 16) / 256;           // 1024  (4 float4/thread)
constexpr int PACK_BLOCKS = (NOUT * (KDIM / 256)) / 8;          // 8192  (1 warp = 256 K-values)
}  // namespace

// Scratch (static device globals: allowed; no runtime allocation).
__device__ __align__(16) __half   g_xh[(size_t)MTOK * KDIM];          // 8 MB fp16 x
__device__ __align__(16) unsigned g_wbits[(KDIM / 32) * NOUT];        // 2 MB packed binarized W, [kword][n]

DINL uint32_t smem_u32(const void* p) {
    uint32_t a;
    asm("{ .reg .u64 t; cvta.to.shared.u64 t, %1; cvt.u32.u64 %0, t; }" : "=r"(a) : "l"(p));
    return a;
}

// ---------------- fused prepass: x->fp16  +  binarize/bit-pack W ----------------
__global__ void __launch_bounds__(256) prepass_kernel(const float* __restrict__ x,
                                                      const float* __restrict__ w) {
    if (blockIdx.x < CONV_BLOCKS) {
        // 4 independent float4 per thread (MLP=4)
        int base = blockIdx.x * 256 + threadIdx.x;
        float4 v[4];
        #pragma unroll
        for (int j = 0; j < 4; ++j)
            v[j] = __ldcs((const float4*)x + base + j * (CONV_BLOCKS * 256));
        #pragma unroll
        for (int j = 0; j < 4; ++j) {
            __half2 h0 = __floats2half2_rn(v[j].x, v[j].y);
            __half2 h1 = __floats2half2_rn(v[j].z, v[j].w);
            uint2 u;
            u.x = *(const uint32_t*)&h0;
            u.y = *(const uint32_t*)&h1;
            *(uint2*)(&g_xh[(size_t)(base + j * (CONV_BLOCKS * 256)) * 4]) = u;
        }
    } else {
        // one warp packs 256 K-values (2x float4/lane) of one W row into 8 bit-words
        int pb = blockIdx.x - CONV_BLOCKS;
        int lane = threadIdx.x & 31;
        int wg = pb * 8 + (threadIdx.x >> 5);   // global warp id
        int n = wg & (NOUT - 1);
        int kb = wg >> 12;                      // 256-wide K block, 0..15
        const float4* src = (const float4*)(w + (size_t)n * KDIM + kb * 256);
        const float4 v0 = __ldcs(src + lane);
        const float4 v1 = __ldcs(src + 32 + lane);
        #pragma unroll
        for (int half = 0; half < 2; ++half) {
            const float4& v = half ? v1 : v0;
            unsigned nib = (v.x > 0.f ? 1u : 0u) | (v.y > 0.f ? 2u : 0u)
                         | (v.z > 0.f ? 4u : 0u) | (v.w > 0.f ? 8u : 0u);
            unsigned a = nib | (__shfl_down_sync(0xFFFFFFFFu, nib, 1) << 4);
            unsigned b = a   | (__shfl_down_sync(0xFFFFFFFFu, a, 2)   << 8);
            unsigned m = b   | (__shfl_down_sync(0xFFFFFFFFu, b, 4)   << 16);
            if ((lane & 7) == 0) {
                int c = kb * 8 + half * 4 + (lane >> 3);
                g_wbits[c * NOUT + n] = m;
            }
        }
    }
}

// ---------------- main GEMM: out = (x_fp16 @ Wb^T) * round(max(s,1)) ----------------
// f16-accumulate HMMA; fp32 promotion every chunk (64 K) via k8 identity-B MMA.
// Half-size CTAs (128 thr, 110KB smem) -> 2 independent CTAs/SM for latency hiding.
__global__ void __launch_bounds__(THREADS, 2)
SBNLinear_39754217292616_kernel(const float* __restrict__ s, float* __restrict__ out) {
    extern __shared__ char smem[];
    const uint32_t sb = smem_u32(smem);
    const int tid = threadIdx.x;
    const int lane = tid & 31;
    const int wid = tid >> 5;                // 0..3
    const int m0 = blockIdx.x * BM;
    const int n0 = blockIdx.y * BN;
    const int m_off = (wid >> 1) * 64;       // 2 warps in M
    const int n_off = (wid & 1) * 64;        // 2 warps in N

    // identity fragment (fp16 I8): serves as B for both k16 and k8 identity MMAs
    const int q = lane >> 2, p = lane & 3;
    const uint32_t idf = ((2 * p == q) ? 0x3C00u : 0u) | ((2 * p + 1 == q) ? 0x3C000000u : 0u);

    float acc32[4][8][4];
    uint32_t acc16[4][8][2];
    #pragma unroll
    for (int mi = 0; mi < 4; ++mi)
        #pragma unroll
        for (int nj = 0; nj < 8; ++nj) {
            acc16[mi][nj][0] = 0u; acc16[mi][nj][1] = 0u;
            #pragma unroll
            for (int e = 0; e < 4; ++e) acc32[mi][nj][e] = 0.0f;
        }

    // A tile: 128 rows x 128B = 1024 x 16B, 8 cp.async per thread
    auto issueA = [&](int c, int buf) {
        #pragma unroll
        for (int i = 0; i < 8; ++i) {
            int qx = tid + i * THREADS;          // 0..1023
            int row = qx >> 3;
            int ch = qx & 7;
            uint32_t dst = sb + buf * STAGE_BYTES + row * A_ROW_B + ch * 16;
            const __half* src = &g_xh[(size_t)(m0 + row) * KDIM + c * BK + ch * 8];
            asm volatile("cp.async.cg.shared.global [%0], [%1], 16;\n" :: "r"(dst), "l"(src) : "memory");
        }
    };
    // one thread per B row: expand 64 bits -> 64 fp16 {0,1} (128B)
    auto stsB = [&](uint2 bits, int buf) {
        uint32_t dst = sb + buf * STAGE_BYTES + A_BYTES + tid * B_ROW_B;
        #pragma unroll
        for (int j = 0; j < 8; ++j) {
            unsigned b8 = ((j < 4 ? bits.x : bits.y) >> ((j & 3) * 8)) & 0xFFu;
            uint32_t u0, u1, u2, u3;
            u0 = (b8 & 1u   ? 0x3C00u : 0u) | (b8 & 2u   ? 0x3C000000u : 0u);
            u1 = (b8 & 4u   ? 0x3C00u : 0u) | (b8 & 8u   ? 0x3C000000u : 0u);
            u2 = (b8 & 16u  ? 0x3C00u : 0u) | (b8 & 32u  ? 0x3C000000u : 0u);
            u3 = (b8 & 64u  ? 0x3C00u : 0u) | (b8 & 128u ? 0x3C000000u : 0u);
            asm volatile("st.shared.v4.b32 [%0], {%1,%2,%3,%4};\n"
                         :: "r"(dst + j * 16), "r"(u0), "r"(u1), "r"(u2), "r"(u3) : "memory");
        }
    };
    auto loadBits = [&](int c) -> uint2 {
        uint2 r;
        r.x = g_wbits[(2 * c) * NOUT + n0 + tid];
        r.y = g_wbits[(2 * c + 1) * NOUT + n0 + tid];
        return r;
    };

    // prologue: stages 0..1
    #pragma unroll
    for (int c = 0; c < STAGES - 1; ++c) {
        issueA(c, c);
        asm volatile("cp.async.commit_group;\n" ::: "memory");
        stsB(loadBits(c), c);
    }
    uint2 bits_next = loadBits(2);

    for (int c = 0; c < NUM_K; ++c) {
        const int buf = c % 3;
        if (c < NUM_K - 2) asm volatile("cp.async.wait_group 1;\n" ::: "memory");
        else               asm volatile("cp.async.wait_group 0;\n" ::: "memory");
        __syncthreads();

        const int cn = c + 2;
        if (cn < NUM_K) {
            const int nbuf = cn % 3;
            stsB(bits_next, nbuf);
            issueA(cn, nbuf);
            asm volatile("cp.async.commit_group;\n" ::: "memory");
            if (cn + 1 < NUM_K)
                bits_next = loadBits(cn + 1);
        }

        const uint32_t ab = sb + buf * STAGE_BYTES;
        const uint32_t bb = ab + A_BYTES;
        #pragma unroll
        for (int h = 0; h < 4; ++h) {
            uint32_t a[4][4];
            #pragma unroll
            for (int mi = 0; mi < 4; ++mi) {
                uint32_t addr = ab + (uint32_t)(m_off + 16 * mi + (lane & 15)) * A_ROW_B
                                   + (uint32_t)(2 * h + (lane >> 4)) * 16;
                asm volatile("ldmatrix.sync.aligned.m8n8.x4.shared.b16 {%0,%1,%2,%3}, [%4];\n"
                             : "=r"(a[mi][0]), "=r"(a[mi][1]), "=r"(a[mi][2]), "=r"(a[mi][3])
                             : "r"(addr));
            }
            #pragma unroll
            for (int g = 0; g < 4; ++g) {
                int row = n_off + 16 * g + ((lane >> 4) << 3) + (lane & 7);
                uint32_t addr = bb + (uint32_t)row * B_ROW_B
                                   + (uint32_t)(2 * h + ((lane >> 3) & 1)) * 16;
                uint32_t r0, r1, r2, r3;
                asm volatile("ldmatrix.sync.aligned.m8n8.x4.shared.b16 {%0,%1,%2,%3}, [%4];\n"
                             : "=r"(r0), "=r"(r1), "=r"(r2), "=r"(r3) : "r"(addr));
                #pragma unroll
                for (int mi = 0; mi < 4; ++mi) {
                    asm volatile(
                        "mma.sync.aligned.m16n8k16.row.col.f16.f16.f16.f16 "
                        "{%0,%1}, {%2,%3,%4,%5}, {%6,%7}, {%0,%1};\n"
                        : "+r"(acc16[mi][2 * g][0]), "+r"(acc16[mi][2 * g][1])
                        : "r"(a[mi][0]), "r"(a[mi][1]), "r"(a[mi][2]), "r"(a[mi][3]),
                          "r"(r0), "r"(r1));
                    asm volatile(
                        "mma.sync.aligned.m16n8k16.row.col.f16.f16.f16.f16 "
                        "{%0,%1}, {%2,%3,%4,%5}, {%6,%7}, {%0,%1};\n"
                        : "+r"(acc16[mi][2 * g + 1][0]), "+r"(acc16[mi][2 * g + 1][1])
                        : "r"(a[mi][0]), "r"(a[mi][1]), "r"(a[mi][2]), "r"(a[mi][3]),
                          "r"(r2), "r"(r3));
                }
            }
        }

        // promote f16 segment accumulators (64 K-steps) into fp32 on the tensor pipe:
        // D-fragment {c01,c23} IS the k8 A-fragment -> acc32 += acc16 x I8 (one k8 MMA each)
        #pragma unroll
        for (int mi = 0; mi < 4; ++mi)
            #pragma unroll
            for (int nj = 0; nj < 8; ++nj) {
                asm volatile(
                    "mma.sync.aligned.m16n8k8.row.col.f32.f16.f16.f32 "
                    "{%0,%1,%2,%3}, {%4,%5}, {%6}, {%0,%1,%2,%3};\n"
                    : "+f"(acc32[mi][nj][0]), "+f"(acc32[mi][nj][1]),
                      "+f"(acc32[mi][nj][2]), "+f"(acc32[mi][nj][3])
                    : "r"(acc16[mi][nj][0]), "r"(acc16[mi][nj][1]), "r"(idf));
                acc16[mi][nj][0] = 0u;
                acc16[mi][nj][1] = 0u;
            }
    }

    // epilogue: fuse s_eff = rint(max(s,1)) and store
    float sc[8][2];
    #pragma unroll
    for (int nj = 0; nj < 8; ++nj) {
        int col = n0 + n_off + 8 * nj + 2 * (lane & 3);
        sc[nj][0] = rintf(fmaxf(s[col], 1.0f));
        sc[nj][1] = rintf(fmaxf(s[col + 1], 1.0f));
    }
    #pragma unroll
    for (int mi = 0; mi < 4; ++mi) {
        int r0 = m0 + m_off + 16 * mi + (lane >> 2);
        #pragma unroll
        for (int nj = 0; nj < 8; ++nj) {
            int col = n0 + n_off + 8 * nj + 2 * (lane & 3);
            float2 v0 = make_float2(acc32[mi][nj][0] * sc[nj][0], acc32[mi][nj][1] * sc[nj][1]);
            float2 v1 = make_float2(acc32[mi][nj][2] * sc[nj][0], acc32[mi][nj][3] * sc[nj][1]);
            *(float2*)(out + (size_t)r0 * NOUT + col) = v0;
            *(float2*)(out + (size_t)(r0 + 8) * NOUT + col) = v1;
        }
    }
}

extern "C" void kernel_launch(void* const* d_in, const int* in_sizes, int n_in,
                              void* d_out, int out_size) {
    (void)in_sizes; (void)n_in; (void)out_size;
    const float* x = (const float*)d_in[0];
    const float* w = (const float*)d_in[1];
    const float* s = (const float*)d_in[2];
    float* out = (float*)d_out;

    prepass_kernel<<<CONV_BLOCKS + PACK_BLOCKS, 256>>>(x, w);

    cudaFuncSetAttribute(SBNLinear_39754217292616_kernel,
                         cudaFuncAttributeMaxDynamicSharedMemorySize, SMEM_TOTAL);
    dim3 grid(MTOK / BM, NOUT / BN);   // 8 x 32 = 256 CTAs, 2 resident/SM
    SBNLinear_39754217292616_kernel<<<grid, THREADS, SMEM_TOTAL>>>(s, out);
}